// round 3
// baseline (speedup 1.0000x reference)
#include <cuda_runtime.h>
#include <cstdint>

// Problem constants (from reference: B=1024, V=100000, C=1024)
#define C_CLUSTERS 1024
#define MAX_B      1024
#define MAX_V      100352   // padded to multiple of 8

// Scratch (allocation-free rule: __device__ globals)
__device__ float g_logdenom[(size_t)MAX_B * C_CLUSTERS];          // [B][C]
__device__ __align__(16) unsigned short g_idx16[MAX_V];           // compact index

// ---------------------------------------------------------------------------
// Pass 0: int32 cluster index -> uint16 (C=1024 fits easily)
// ---------------------------------------------------------------------------
__global__ void idx_convert_kernel(const int* __restrict__ idx, int V) {
    int i = blockIdx.x * blockDim.x + threadIdx.x;
    if (i < V) g_idx16[i] = (unsigned short)idx[i];
}

// ---------------------------------------------------------------------------
// Pass 1: per-row segment sum of exp(logits), then log(clip(.)) epilogue.
// One block per row b. sums live in shared memory (4 KB), atomicAdd scatter.
// ---------------------------------------------------------------------------
__global__ __launch_bounds__(512, 2)
void pass1_kernel(const float* __restrict__ logits, int B, int V) {
    __shared__ float s_sum[C_CLUSTERS];
    const int b   = blockIdx.x;
    const int tid = threadIdx.x;
    const int nt  = blockDim.x;

    for (int i = tid; i < C_CLUSTERS; i += nt) s_sum[i] = 0.0f;
    __syncthreads();

    const float* row = logits + (size_t)b * V;
    const int V4 = V >> 2;
    const float4*  row4 = (const float4*)row;
    const ushort4* idx4 = (const ushort4*)g_idx16;

    for (int i = tid; i < V4; i += nt) {
        float4  x = row4[i];
        ushort4 c = idx4[i];
        atomicAdd(&s_sum[c.x], __expf(x.x));
        atomicAdd(&s_sum[c.y], __expf(x.y));
        atomicAdd(&s_sum[c.z], __expf(x.z));
        atomicAdd(&s_sum[c.w], __expf(x.w));
    }
    // tail (V % 4)
    for (int i = (V4 << 2) + tid; i < V; i += nt) {
        atomicAdd(&s_sum[g_idx16[i]], __expf(row[i]));
    }
    __syncthreads();

    float* drow = g_logdenom + (size_t)b * C_CLUSTERS;
    for (int i = tid; i < C_CLUSTERS; i += nt) {
        drow[i] = logf(fmaxf(s_sum[i], 1e-20f)); // SAFE_LOG_MIN clamp
    }
}

// ---------------------------------------------------------------------------
// Pass 2: out[b][v] = (c==0) ? log_sigmoid(x) : x - logdenom[b][c]
// log_sigmoid(x) = x - log1p(exp(x))
// Pure streaming read/write + L2-hot gathers of logdenom (4 MB) and idx16.
// ---------------------------------------------------------------------------
__global__ __launch_bounds__(256)
void pass2_kernel(const float* __restrict__ logits, float* __restrict__ out,
                  int B, int V) {
    const int b = blockIdx.y;
    const float* row  = logits + (size_t)b * V;
    float*       orow = out    + (size_t)b * V;
    const float* drow = g_logdenom + (size_t)b * C_CLUSTERS;

    const int V4 = V >> 2;
    const float4*  row4  = (const float4*)row;
    float4*        orow4 = (float4*)orow;
    const ushort4* idx4  = (const ushort4*)g_idx16;

    const int i0     = blockIdx.x * blockDim.x + threadIdx.x;
    const int stride = gridDim.x * blockDim.x;

    for (int i = i0; i < V4; i += stride) {
        float4  x = row4[i];
        ushort4 c = idx4[i];
        float4 r;
        r.x = (c.x == 0) ? (x.x - log1pf(__expf(x.x))) : (x.x - drow[c.x]);
        r.y = (c.y == 0) ? (x.y - log1pf(__expf(x.y))) : (x.y - drow[c.y]);
        r.z = (c.z == 0) ? (x.z - log1pf(__expf(x.z))) : (x.z - drow[c.z]);
        r.w = (c.w == 0) ? (x.w - log1pf(__expf(x.w))) : (x.w - drow[c.w]);
        orow4[i] = r;
    }
    // tail (V % 4)
    for (int i = (V4 << 2) + i0; i < V; i += stride) {
        float x = row[i];
        unsigned short c = g_idx16[i];
        orow[i] = (c == 0) ? (x - log1pf(__expf(x))) : (x - drow[c]);
    }
}

// ---------------------------------------------------------------------------
extern "C" void kernel_launch(void* const* d_in, const int* in_sizes, int n_in,
                              void* d_out, int out_size) {
    const float* logits = (const float*)d_in[0];
    const int*   cidx   = (const int*)d_in[1];   // int32 (JAX x64 disabled)
    const int V = in_sizes[1];
    const int B = in_sizes[0] / V;

    // Pass 0: index conversion (tiny)
    {
        int threads = 256;
        int blocks  = (V + threads - 1) / threads;
        idx_convert_kernel<<<blocks, threads>>>(cidx, V);
    }

    // Pass 1: per-row segment sums + log epilogue
    pass1_kernel<<<B, 512>>>(logits, B, V);

    // Pass 2: streaming output
    {
        int threads = 256;
        int V4      = V >> 2;
        int gx      = (V4 + threads - 1) / threads;
        dim3 grid(gx, B, 1);
        pass2_kernel<<<grid, threads>>>(logits, (float*)d_out, B, V);
    }
}

// round 5
// speedup vs baseline: 1.0719x; 1.0719x over previous
#include <cuda_runtime.h>
#include <cstdint>

// Problem constants (from reference: B=1024, V=100000, C=1024)
#define C_CLUSTERS 1024
#define MAX_B      1024
#define MAX_V      100352   // padded to multiple of 8

// Scratch (allocation-free rule: __device__ globals)
__device__ float g_logdenom[(size_t)MAX_B * C_CLUSTERS];          // [B][C]
__device__ __align__(16) unsigned short g_idx16[MAX_V];           // compact index

// ---------------------------------------------------------------------------
// Pass 0: int32 cluster index -> uint16 (C=1024 fits easily)
// ---------------------------------------------------------------------------
__global__ void idx_convert_kernel(const int* __restrict__ idx, int V) {
    int i = blockIdx.x * blockDim.x + threadIdx.x;
    if (i < V) g_idx16[i] = (unsigned short)idx[i];
}

// ---------------------------------------------------------------------------
// Pass 1: per-row segment sum of exp(logits), then log(clip(.)) epilogue.
// One block per row b. sums live in shared memory (4 KB), atomicAdd scatter.
// ---------------------------------------------------------------------------
__global__ __launch_bounds__(512, 2)
void pass1_kernel(const float* __restrict__ logits, int B, int V) {
    __shared__ float s_sum[C_CLUSTERS];
    const int b   = blockIdx.x;
    const int tid = threadIdx.x;
    const int nt  = blockDim.x;

    for (int i = tid; i < C_CLUSTERS; i += nt) s_sum[i] = 0.0f;
    __syncthreads();

    const float* row = logits + (size_t)b * V;
    const int V4 = V >> 2;
    const float4*  row4 = (const float4*)row;
    const ushort4* idx4 = (const ushort4*)g_idx16;

    for (int i = tid; i < V4; i += nt) {
        float4  x = row4[i];
        ushort4 c = idx4[i];
        atomicAdd(&s_sum[c.x], __expf(x.x));
        atomicAdd(&s_sum[c.y], __expf(x.y));
        atomicAdd(&s_sum[c.z], __expf(x.z));
        atomicAdd(&s_sum[c.w], __expf(x.w));
    }
    // tail (V % 4)
    for (int i = (V4 << 2) + tid; i < V; i += nt) {
        atomicAdd(&s_sum[g_idx16[i]], __expf(row[i]));
    }
    __syncthreads();

    float* drow = g_logdenom + (size_t)b * C_CLUSTERS;
    for (int i = tid; i < C_CLUSTERS; i += nt) {
        drow[i] = logf(fmaxf(s_sum[i], 1e-20f)); // SAFE_LOG_MIN clamp
    }
}

// ---------------------------------------------------------------------------
// Pass 2: out[b][v] = (c==0) ? log_sigmoid(x) : x - logdenom[b][c]
// log_sigmoid(x) = x - log1p(exp(x))
// Table cached in SHARED memory: random gathers become ~3-conflict LDS
// instead of up-to-32-wavefront L1 LDG replays.
// ---------------------------------------------------------------------------
#define P2_SPLITS 4
__global__ __launch_bounds__(512)
void pass2_kernel(const float* __restrict__ logits, float* __restrict__ out,
                  int B, int V) {
    __shared__ float s_d[C_CLUSTERS];
    const int b = blockIdx.y;
    const float* drow = g_logdenom + (size_t)b * C_CLUSTERS;
    for (int i = threadIdx.x; i < C_CLUSTERS; i += blockDim.x) s_d[i] = drow[i];
    __syncthreads();

    const float* row  = logits + (size_t)b * V;
    float*       orow = out    + (size_t)b * V;

    const int V4 = V >> 2;
    const float4*  row4  = (const float4*)row;
    float4*        orow4 = (float4*)orow;
    const ushort4* idx4  = (const ushort4*)g_idx16;

    const int chunk = (V4 + P2_SPLITS - 1) / P2_SPLITS;
    const int start = blockIdx.x * chunk;
    const int end   = min(start + chunk, V4);

    for (int i = start + (int)threadIdx.x; i < end; i += (int)blockDim.x) {
        float4  x = row4[i];
        ushort4 c = idx4[i];
        float4 r;
        r.x = (c.x == 0) ? (x.x - log1pf(__expf(x.x))) : (x.x - s_d[c.x]);
        r.y = (c.y == 0) ? (x.y - log1pf(__expf(x.y))) : (x.y - s_d[c.y]);
        r.z = (c.z == 0) ? (x.z - log1pf(__expf(x.z))) : (x.z - s_d[c.z]);
        r.w = (c.w == 0) ? (x.w - log1pf(__expf(x.w))) : (x.w - s_d[c.w]);
        orow4[i] = r;
    }
    // tail (V % 4) — handled by last x-block
    if (blockIdx.x == P2_SPLITS - 1) {
        for (int i = (V4 << 2) + (int)threadIdx.x; i < V; i += (int)blockDim.x) {
            float x = row[i];
            unsigned short c = g_idx16[i];
            orow[i] = (c == 0) ? (x - log1pf(__expf(x))) : (x - s_d[c]);
        }
    }
}

// ---------------------------------------------------------------------------
extern "C" void kernel_launch(void* const* d_in, const int* in_sizes, int n_in,
                              void* d_out, int out_size) {
    const float* logits = (const float*)d_in[0];
    const int*   cidx   = (const int*)d_in[1];   // int32 (JAX x64 disabled)
    const int V = in_sizes[1];
    const int B = in_sizes[0] / V;

    // Pass 0: index conversion (tiny)
    {
        int threads = 256;
        int blocks  = (V + threads - 1) / threads;
        idx_convert_kernel<<<blocks, threads>>>(cidx, V);
    }

    // Pass 1: per-row segment sums + log epilogue
    pass1_kernel<<<B, 512>>>(logits, B, V);

    // Pass 2: streaming output with smem-cached denominator table
    {
        dim3 grid(P2_SPLITS, B, 1);
        pass2_kernel<<<grid, 512>>>(logits, (float*)d_out, B, V);
    }
}